// round 16
// baseline (speedup 1.0000x reference)
#include <cuda_runtime.h>
#include <math.h>
#include <stdint.h>

// ---------------------------------------------------------------------------
// Problem constants
// ---------------------------------------------------------------------------
namespace {
constexpr int kD   = 256;
constexpr int kNH  = 8;
constexpr int kDH  = 32;
constexpr int kNL  = 4;
constexpr int kNP  = 4;
constexpr int kDFF = 1024;
constexpr int kBS  = 8;
constexpr int kNQ  = 300;
constexpr int kS   = 19947;
constexpr int kMQ  = kBS * kNQ;      // 2400
constexpr int kHK  = 288;            // per-head agg K: 256 + bsum + 31 pad
constexpr int kAK2 = kNH * kHK;      // 2304 agg row width
constexpr int kOW  = 384;            // merged offs(256) + awl(128) width

constexpr size_t OFF_QKADD = 0;
constexpr size_t OFF_QKV   = OFF_QKADD + (size_t)kMQ * kD;   // [2400][768]
constexpr size_t OFF_ATTN  = OFF_QKV   + (size_t)kMQ * 768;
constexpr size_t OFF_TGT1  = OFF_ATTN  + (size_t)kMQ * kD;
constexpr size_t OFF_QUERY = OFF_TGT1  + (size_t)kMQ * kD;
constexpr size_t OFF_OA    = OFF_QUERY + (size_t)kMQ * kD;   // [2400][384]
constexpr size_t OFF_TGT2  = OFF_OA    + (size_t)kMQ * kOW;
constexpr size_t OFF_HID   = OFF_TGT2  + (size_t)kMQ * kD;
constexpr size_t OFF_FFO   = OFF_HID   + (size_t)kMQ * kDFF;
constexpr size_t OFF_Y     = OFF_FFO   + (size_t)kMQ * kD;   // [2400][256]
constexpr size_t OFF_AGG   = OFF_Y     + (size_t)kMQ * kD;   // [2400][2304]
constexpr size_t OFF_WV2   = OFF_AGG   + (size_t)kMQ * kAK2; // [8][32][288]
constexpr size_t OFF_WCAT  = OFF_WV2   + (size_t)kNH * 32 * kHK;
constexpr size_t OFF_BCAT  = OFF_WCAT  + (size_t)kOW * kD;   // [384]
constexpr size_t SCRATCH_TOTAL = OFF_BCAT + kOW;
} // namespace

__device__ float g_scratch[SCRATCH_TOTAL];

// ---------------------------------------------------------------------------
// helpers
// ---------------------------------------------------------------------------
__device__ __forceinline__ uint32_t smem_u32(const void* p) {
    uint32_t a;
    asm("{ .reg .u64 t; cvta.to.shared.u64 t, %1; cvt.u32.u64 %0, t; }"
        : "=r"(a) : "l"(p));
    return a;
}

__device__ __forceinline__ void cp_async16(uint32_t dst, const void* src, bool pred) {
    int sz = pred ? 16 : 0;
    asm volatile("cp.async.cg.shared.global [%0], [%1], 16, %2;"
                 :: "r"(dst), "l"(src), "r"(sz));
}
__device__ __forceinline__ void cp_commit() {
    asm volatile("cp.async.commit_group;");
}
template <int N>
__device__ __forceinline__ void cp_wait() {
    asm volatile("cp.async.wait_group %0;" :: "n"(N));
}

__device__ __forceinline__ void mma_tf32(float (&d)[4],
                                         const uint32_t (&a)[4],
                                         const uint32_t (&b)[2]) {
    asm volatile(
        "mma.sync.aligned.m16n8k8.row.col.f32.tf32.tf32.f32 "
        "{%0,%1,%2,%3}, {%4,%5,%6,%7}, {%8,%9}, {%0,%1,%2,%3};"
        : "+f"(d[0]), "+f"(d[1]), "+f"(d[2]), "+f"(d[3])
        : "r"(a[0]), "r"(a[1]), "r"(a[2]), "r"(a[3]),
          "r"(b[0]), "r"(b[1]));
}

// ---------------------------------------------------------------------------
// TF32 tensor-core GEMM with per-n-region A select and optional split-K.
// ---------------------------------------------------------------------------
template <int STAGES, bool RELU, int SPLITK>
__global__ __launch_bounds__(256, 2)
void gemm_tf32_kernel(const float* __restrict__ A1,
                      const float* __restrict__ A2,
                      int n_split,
                      const float* __restrict__ W,
                      const float* __restrict__ bias,
                      float* __restrict__ C,
                      int M, int N, int K) {
    constexpr int BM = 64, BN = 64, BK = 32;
    constexpr int LD = BK + 4;                 // 36 words/row
    constexpr int THREADS = 256;
    constexpr int WM = 2;
    constexpr int MT = 2, NT = 2;
    constexpr int A_IT = (BM * BK / 4) / THREADS;   // 2
    constexpr int B_IT = (BN * BK / 4) / THREADS;   // 2

    extern __shared__ float smem[];
    float* As = smem;
    float* Ws = smem + (size_t)STAGES * BM * LD;

    const int tid  = threadIdx.x;
    const int warp = tid >> 5;
    const int lane = tid & 31;
    const int g    = lane >> 2;
    const int tg   = lane & 3;
    const int tm   = blockIdx.y * BM;
    const int tn   = blockIdx.x * BN;
    const int wm   = (warp % WM) * 32;
    const int wn   = (warp / WM) * 16;

    const float* A = (tn < n_split) ? A1 : A2;

    const int nk_all = K / BK;
    const int nk_per = (nk_all + SPLITK - 1) / SPLITK;
    const int k_lo   = (SPLITK > 1) ? blockIdx.z * nk_per : 0;
    const int k_hi   = (SPLITK > 1) ? ((k_lo + nk_per < nk_all) ? k_lo + nk_per
                                                                : nk_all)
                                    : nk_all;
    const int nk_this = k_hi - k_lo;

    float acc[MT][NT][4] = {};

    auto issue = [&](int s, int kt) {
        if (kt < nk_this) {
            const int k0 = (k_lo + kt) * BK;
#pragma unroll
            for (int i = 0; i < A_IT; ++i) {
                int idx = tid + i * THREADS;
                int r = idx >> 3, c4 = (idx & 7) * 4;
                int gr = tm + r;
                cp_async16(smem_u32(&As[(size_t)s * BM * LD + r * LD + c4]),
                           A + (size_t)gr * K + k0 + c4, gr < M);
            }
#pragma unroll
            for (int i = 0; i < B_IT; ++i) {
                int idx = tid + i * THREADS;
                int r = idx >> 3, c4 = (idx & 7) * 4;
                cp_async16(smem_u32(&Ws[(size_t)s * BN * LD + r * LD + c4]),
                           W + (size_t)(tn + r) * K + k0 + c4, true);
            }
        }
        cp_commit();
    };

    issue(0, 0);
#pragma unroll
    for (int p = 1; p < STAGES - 1; ++p) issue(p, p);

    for (int kt = 0; kt < nk_this; ++kt) {
        const int s = kt % STAGES;
        cp_wait<STAGES - 2>();
        __syncthreads();
        issue((kt + STAGES - 1) % STAGES, kt + STAGES - 1);

        const float* as = &As[(size_t)s * BM * LD];
        const float* ws = &Ws[(size_t)s * BN * LD];
#pragma unroll
        for (int ks = 0; ks < 4; ++ks) {
            const int kc = ks * 8 + tg;
            uint32_t af[MT][4], bf[NT][2];
#pragma unroll
            for (int mt = 0; mt < MT; ++mt) {
                const int r = wm + mt * 16 + g;
                af[mt][0] = __float_as_uint(as[r * LD + kc]);
                af[mt][1] = __float_as_uint(as[(r + 8) * LD + kc]);
                af[mt][2] = __float_as_uint(as[r * LD + kc + 4]);
                af[mt][3] = __float_as_uint(as[(r + 8) * LD + kc + 4]);
            }
#pragma unroll
            for (int nt = 0; nt < NT; ++nt) {
                const int n = wn + nt * 8 + g;
                bf[nt][0] = __float_as_uint(ws[n * LD + kc]);
                bf[nt][1] = __float_as_uint(ws[n * LD + kc + 4]);
            }
#pragma unroll
            for (int mt = 0; mt < MT; ++mt)
#pragma unroll
                for (int nt = 0; nt < NT; ++nt)
                    mma_tf32(acc[mt][nt], af[mt], bf[nt]);
        }
        __syncthreads();
    }

    const bool add_bias = (SPLITK == 1) || (blockIdx.z == 0);
#pragma unroll
    for (int mt = 0; mt < MT; ++mt) {
        const int gr0 = tm + wm + mt * 16 + g;
        const int gr1 = gr0 + 8;
#pragma unroll
        for (int nt = 0; nt < NT; ++nt) {
            const int gc = tn + wn + nt * 8 + tg * 2;
            const float b0 = add_bias ? bias[gc] : 0.f;
            const float b1 = add_bias ? bias[gc + 1] : 0.f;
            if (gr0 < M) {
                float v0 = acc[mt][nt][0] + b0;
                float v1 = acc[mt][nt][1] + b1;
                if (RELU) { v0 = fmaxf(v0, 0.f); v1 = fmaxf(v1, 0.f); }
                if (SPLITK == 1) {
                    *(float2*)(C + (size_t)gr0 * N + gc) = make_float2(v0, v1);
                } else {
                    atomicAdd(C + (size_t)gr0 * N + gc, v0);
                    atomicAdd(C + (size_t)gr0 * N + gc + 1, v1);
                }
            }
            if (gr1 < M) {
                float v2 = acc[mt][nt][2] + b0;
                float v3 = acc[mt][nt][3] + b1;
                if (RELU) { v2 = fmaxf(v2, 0.f); v3 = fmaxf(v3, 0.f); }
                if (SPLITK == 1) {
                    *(float2*)(C + (size_t)gr1 * N + gc) = make_float2(v2, v3);
                } else {
                    atomicAdd(C + (size_t)gr1 * N + gc, v2);
                    atomicAdd(C + (size_t)gr1 * N + gc + 1, v3);
                }
            }
        }
    }
}

template <int STAGES>
constexpr int gemm_smem_bytes() { return STAGES * 128 * 36 * 4; }

// ---------------------------------------------------------------------------
// Fused GEMM + residual + LayerNorm (+ optional out2 = ln + pos).
//   out[M,256] = LN( xres + A[M,K] @ W[256,K]^T + bias )
// BM=16, BN=256 (full row per CTA), BK=32, 2-stage cp.async, grid = M/16.
// Warp w owns n-strip [w*32, w*32+32); epilogue stages to SMEM then each
// warp LNs 2 rows. Requires M % 16 == 0, K % 32 == 0.
// ---------------------------------------------------------------------------
template <bool WITH_POS>
__global__ __launch_bounds__(256, 2)
void gemm_ln_kernel(const float* __restrict__ A,
                    const float* __restrict__ W,
                    const float* __restrict__ bias,
                    const float* __restrict__ xres,
                    const float* __restrict__ gam,
                    const float* __restrict__ bet,
                    const float* __restrict__ pos,
                    float* __restrict__ out,
                    float* __restrict__ out2,
                    int K) {
    constexpr int BM = 16, BK = 32;
    constexpr int LD = 36;
    constexpr int SVLD = 288;
    extern __shared__ float smem[];
    float* As = smem;                         // 2 * 16 * 36
    float* Ws = smem + 2 * BM * LD;           // 2 * 256 * 36
    float* Sv = smem;                         // reused after K loop: [16][288]

    const int tid  = threadIdx.x;
    const int w    = tid >> 5;
    const int lane = tid & 31;
    const int g    = lane >> 2;
    const int tg   = lane & 3;
    const int tm   = blockIdx.x * BM;
    const int wn   = w * 32;

    float acc[4][4] = {};
    const int NK = K / BK;

    auto issue = [&](int s, int kt) {
        if (kt < NK) {
            const int k0 = kt * BK;
            if (tid < 128) {
                int r = tid >> 3, c4 = (tid & 7) * 4;
                cp_async16(smem_u32(&As[s * BM * LD + r * LD + c4]),
                           A + (size_t)(tm + r) * K + k0 + c4, true);
            }
#pragma unroll
            for (int i = 0; i < 8; ++i) {
                int idx = tid + i * 256;
                int r = idx >> 3, c4 = (idx & 7) * 4;
                cp_async16(smem_u32(&Ws[s * 256 * LD + r * LD + c4]),
                           W + (size_t)r * K + k0 + c4, true);
            }
        }
        cp_commit();
    };

    issue(0, 0);
    for (int kt = 0; kt < NK; ++kt) {
        const int s = kt & 1;
        cp_wait<0>();
        __syncthreads();
        issue(s ^ 1, kt + 1);
        const float* as = &As[s * BM * LD];
        const float* ws = &Ws[s * 256 * LD];
#pragma unroll
        for (int ks = 0; ks < 4; ++ks) {
            const int kc = ks * 8 + tg;
            uint32_t af[4];
            af[0] = __float_as_uint(as[g * LD + kc]);
            af[1] = __float_as_uint(as[(g + 8) * LD + kc]);
            af[2] = __float_as_uint(as[g * LD + kc + 4]);
            af[3] = __float_as_uint(as[(g + 8) * LD + kc + 4]);
#pragma unroll
            for (int nt = 0; nt < 4; ++nt) {
                uint32_t bf[2];
                const int n = wn + nt * 8 + g;
                bf[0] = __float_as_uint(ws[n * LD + kc]);
                bf[1] = __float_as_uint(ws[n * LD + kc + 4]);
                mma_tf32(acc[nt], af, bf);
            }
        }
    }
    __syncthreads();

    // stage gemm+bias into Sv
#pragma unroll
    for (int nt = 0; nt < 4; ++nt) {
        const int col = wn + nt * 8 + tg * 2;
        const float b0 = bias[col], b1 = bias[col + 1];
        Sv[g * SVLD + col]           = acc[nt][0] + b0;
        Sv[g * SVLD + col + 1]       = acc[nt][1] + b1;
        Sv[(g + 8) * SVLD + col]     = acc[nt][2] + b0;
        Sv[(g + 8) * SVLD + col + 1] = acc[nt][3] + b1;
    }
    __syncthreads();

    // per-row residual + LN: warp w handles rows 2w, 2w+1
#pragma unroll
    for (int rr = 0; rr < 2; ++rr) {
        const int r = w * 2 + rr;
        const int gr = tm + r;
        const size_t base = (size_t)gr * kD + lane * 8;
        float v[8];
        {
            float4 s0 = *(float4*)&Sv[r * SVLD + lane * 8];
            float4 s1 = *(float4*)&Sv[r * SVLD + lane * 8 + 4];
            float4 x0 = *(const float4*)(xres + base);
            float4 x1 = *(const float4*)(xres + base + 4);
            v[0] = s0.x + x0.x; v[1] = s0.y + x0.y;
            v[2] = s0.z + x0.z; v[3] = s0.w + x0.w;
            v[4] = s1.x + x1.x; v[5] = s1.y + x1.y;
            v[6] = s1.z + x1.z; v[7] = s1.w + x1.w;
        }
        float s = 0.f;
#pragma unroll
        for (int i = 0; i < 8; ++i) s += v[i];
#pragma unroll
        for (int o2 = 16; o2 > 0; o2 >>= 1) s += __shfl_xor_sync(~0u, s, o2);
        const float mean = s * (1.f / kD);
        float s2 = 0.f;
#pragma unroll
        for (int i = 0; i < 8; ++i) { float d = v[i] - mean; s2 += d * d; }
#pragma unroll
        for (int o2 = 16; o2 > 0; o2 >>= 1) s2 += __shfl_xor_sync(~0u, s2, o2);
        const float inv = rsqrtf(s2 * (1.f / kD) + 1e-5f);

        float4 g0 = *(const float4*)(gam + lane * 8);
        float4 g1 = *(const float4*)(gam + lane * 8 + 4);
        float4 b0 = *(const float4*)(bet + lane * 8);
        float4 b1 = *(const float4*)(bet + lane * 8 + 4);
        float o[8];
        o[0] = (v[0] - mean) * inv * g0.x + b0.x;
        o[1] = (v[1] - mean) * inv * g0.y + b0.y;
        o[2] = (v[2] - mean) * inv * g0.z + b0.z;
        o[3] = (v[3] - mean) * inv * g0.w + b0.w;
        o[4] = (v[4] - mean) * inv * g1.x + b1.x;
        o[5] = (v[5] - mean) * inv * g1.y + b1.y;
        o[6] = (v[6] - mean) * inv * g1.z + b1.z;
        o[7] = (v[7] - mean) * inv * g1.w + b1.w;
        *(float4*)(out + base)     = make_float4(o[0], o[1], o[2], o[3]);
        *(float4*)(out + base + 4) = make_float4(o[4], o[5], o[6], o[7]);
        if (WITH_POS) {
            float4 p0 = *(const float4*)(pos + base);
            float4 p1 = *(const float4*)(pos + base + 4);
            *(float4*)(out2 + base) =
                make_float4(o[0] + p0.x, o[1] + p0.y, o[2] + p0.z, o[3] + p0.w);
            *(float4*)(out2 + base + 4) =
                make_float4(o[4] + p1.x, o[5] + p1.y, o[6] + p1.z, o[7] + p1.w);
        }
    }
}

constexpr int gemm_ln_smem_bytes() { return 2 * (16 + 256) * 36 * 4; }  // 78336

// ---------------------------------------------------------------------------
// Stage-1 batched head GEMM: y[m][h*32+j] = agg[m][h*288..] @ Wv2[h][j][.]^T
// ---------------------------------------------------------------------------
__global__ __launch_bounds__(256, 2)
void gemm_stage1_kernel(const float* __restrict__ agg,
                        const float* __restrict__ wv2,
                        float* __restrict__ y) {
    constexpr int BM = 64, BN = 32, BK = 32, STAGES = 3;
    constexpr int LD = BK + 4;
    constexpr int THREADS = 256;
    constexpr int NK = kHK / BK;                 // 9

    extern __shared__ float smem[];
    float* As = smem;
    float* Ws = smem + (size_t)STAGES * BM * LD;

    const int tid  = threadIdx.x;
    const int warp = tid >> 5;
    const int lane = tid & 31;
    const int g    = lane >> 2;
    const int tg   = lane & 3;
    const int tm   = blockIdx.x * BM;
    const int h    = blockIdx.y;
    const int wm   = (warp & 1) * 32;
    const int wn   = (warp >> 1) * 8;

    const float* A = agg + (size_t)h * kHK;
    const float* W = wv2 + (size_t)h * 32 * kHK;

    float acc[2][4] = {};

    auto issue = [&](int s, int kt) {
        if (kt < NK) {
            const int k0 = kt * BK;
#pragma unroll
            for (int i = 0; i < 2; ++i) {
                int idx = tid + i * THREADS;
                int r = idx >> 3, c4 = (idx & 7) * 4;
                int gr = tm + r;
                cp_async16(smem_u32(&As[(size_t)s * BM * LD + r * LD + c4]),
                           A + (size_t)gr * kAK2 + k0 + c4, gr < kMQ);
            }
            {
                int r = tid >> 3, c4 = (tid & 7) * 4;
                cp_async16(smem_u32(&Ws[(size_t)s * BN * LD + r * LD + c4]),
                           W + (size_t)r * kHK + k0 + c4, true);
            }
        }
        cp_commit();
    };

    issue(0, 0);
    issue(1, 1);

    for (int kt = 0; kt < NK; ++kt) {
        const int s = kt % STAGES;
        cp_wait<1>();
        __syncthreads();
        issue((kt + 2) % STAGES, kt + 2);

        const float* as = &As[(size_t)s * BM * LD];
        const float* ws = &Ws[(size_t)s * BN * LD];
#pragma unroll
        for (int ks = 0; ks < 4; ++ks) {
            const int kc = ks * 8 + tg;
            uint32_t af[4], bf[2];
            const int r = wm + g;
            af[0] = __float_as_uint(as[r * LD + kc]);
            af[1] = __float_as_uint(as[(r + 8) * LD + kc]);
            af[2] = __float_as_uint(as[r * LD + kc + 4]);
            af[3] = __float_as_uint(as[(r + 8) * LD + kc + 4]);
            const int n = wn + g;
            bf[0] = __float_as_uint(ws[n * LD + kc]);
            bf[1] = __float_as_uint(ws[n * LD + kc + 4]);
            mma_tf32(acc[0], af, bf);
            const int r2 = r + 16;
            af[0] = __float_as_uint(as[r2 * LD + kc]);
            af[1] = __float_as_uint(as[(r2 + 8) * LD + kc]);
            af[2] = __float_as_uint(as[r2 * LD + kc + 4]);
            af[3] = __float_as_uint(as[(r2 + 8) * LD + kc + 4]);
            mma_tf32(acc[1], af, bf);
        }
        __syncthreads();
    }

#pragma unroll
    for (int mt = 0; mt < 2; ++mt) {
        const int gr0 = tm + wm + mt * 16 + g;
        const int gr1 = gr0 + 8;
        const int gc = h * 32 + wn + tg * 2;
        if (gr0 < kMQ)
            *(float2*)(y + (size_t)gr0 * kD + gc) =
                make_float2(acc[mt][0], acc[mt][1]);
        if (gr1 < kMQ)
            *(float2*)(y + (size_t)gr1 * kD + gc) =
                make_float2(acc[mt][2], acc[mt][3]);
    }
}

constexpr int stage1_smem_bytes() { return 3 * (64 + 32) * 36 * 4; }

// ---------------------------------------------------------------------------
// Precompute kernel. grid = (8, 9), block = 256.
// ---------------------------------------------------------------------------
__global__ void precompute_kernel(const float* __restrict__ v_w,
                                  const float* __restrict__ v_b,
                                  const float* __restrict__ so_w,
                                  const float* __restrict__ so_b,
                                  const float* __restrict__ aw_w,
                                  const float* __restrict__ aw_b,
                                  float* __restrict__ wv2,
                                  float* __restrict__ wcat,
                                  float* __restrict__ bcat) {
    const int tid = threadIdx.x;
    if (blockIdx.y == 8) {
        const int r0 = blockIdx.x * 48;
        for (int r = r0; r < r0 + 48; ++r) {
            const float* src = (r < 256) ? (so_w + (size_t)r * 256)
                                         : (aw_w + (size_t)(r - 256) * 256);
            wcat[(size_t)r * 256 + tid] = src[tid];
        }
        if (tid < 48) {
            int r = r0 + tid;
            bcat[r] = (r < 256) ? so_b[r] : aw_b[r - 256];
        }
        return;
    }
    if (blockIdx.x > 0) return;
    const int h = blockIdx.y;
    float* dst = wv2 + (size_t)h * 32 * kHK;
    for (int idx = tid; idx < 32 * kHK; idx += 256) {
        const int j = idx / kHK, c = idx % kHK;
        float v = 0.f;
        if (c < 256)      v = v_w[(size_t)(32 * h + j) * 256 + c];
        else if (c == 256) v = v_b[32 * h + j];
        dst[idx] = v;
    }
}

// ---------------------------------------------------------------------------
// Elementwise add
// ---------------------------------------------------------------------------
__global__ void add_kernel(const float* __restrict__ a,
                           const float* __restrict__ b,
                           float* __restrict__ out, int n) {
    int i = blockIdx.x * blockDim.x + threadIdx.x;
    if (i < n) out[i] = a[i] + b[i];
}

// ---------------------------------------------------------------------------
// Residual + LayerNorm (final LN3).
// ---------------------------------------------------------------------------
__global__ void add_ln_kernel(const float* __restrict__ x,
                              const float* __restrict__ r,
                              const float* __restrict__ g,
                              const float* __restrict__ bta,
                              float* __restrict__ out) {
    const int row = blockIdx.x;
    const int t = threadIdx.x;
    const size_t base = (size_t)row * kD;
    float v = x[base + t] + r[base + t];

    __shared__ float sm[8];
    float s = v;
#pragma unroll
    for (int o = 16; o > 0; o >>= 1) s += __shfl_xor_sync(~0u, s, o);
    if ((t & 31) == 0) sm[t >> 5] = s;
    __syncthreads();
    float tot = 0.f;
#pragma unroll
    for (int i = 0; i < 8; ++i) tot += sm[i];
    const float mean = tot * (1.f / kD);
    const float d = v - mean;
    float s2 = d * d;
#pragma unroll
    for (int o = 16; o > 0; o >>= 1) s2 += __shfl_xor_sync(~0u, s2, o);
    __syncthreads();
    if ((t & 31) == 0) sm[t >> 5] = s2;
    __syncthreads();
    float tot2 = 0.f;
#pragma unroll
    for (int i = 0; i < 8; ++i) tot2 += sm[i];
    const float var = tot2 * (1.f / kD);
    out[base + t] = d * rsqrtf(var + 1e-5f) * g[t] + bta[t];
}

// ---------------------------------------------------------------------------
// Tensor-core self attention, 32-query tile, software-pipelined fragments.
// ---------------------------------------------------------------------------
namespace {
constexpr int kQT   = 32;
constexpr int kSLD  = 316;
constexpr int kKLD2 = 36;
constexpr int kVLD2 = 308;
constexpr int S_FLOATS  = kQT * kSLD;
constexpr int KV_FLOATS = kNQ * kKLD2;
constexpr int ATTN_SMEM = (S_FLOATS + KV_FLOATS + kQT) * 4;  // 83776 B
}

__global__ __launch_bounds__(256, 2)
void attn_tc_kernel(const float* __restrict__ qkv, float* __restrict__ o) {
    extern __shared__ float sm[];
    float* S    = sm;
    float* KV   = sm + S_FLOATS;
    float* lrow = KV + KV_FLOATS;

    const int tid  = threadIdx.x;
    const int w    = tid >> 5;
    const int lane = tid & 31;
    const int g    = lane >> 2;
    const int tg   = lane & 3;
    const int h  = blockIdx.y;
    const int b  = blockIdx.z;
    const int q0 = blockIdx.x * kQT;
    const float scale = 0.1767766952966369f;

    for (int idx = tid; idx < kNQ * 8; idx += 256) {
        const int r = idx >> 3, c4 = (idx & 7) * 4;
        *(float4*)&KV[r * kKLD2 + c4] =
            *(const float4*)(qkv + ((size_t)(b * kNQ + r)) * 768 + 256 +
                             h * kDH + c4);
    }
    __syncthreads();

    const int mstrip = w & 1;
    const int lr_g   = mstrip * 16 + g;
    const int kq     = w >> 1;
    uint32_t qf[4][4];
    {
        int grow0 = b * kNQ + q0 + lr_g;
        int grow1 = grow0 + 8;
        if (grow0 > kMQ - 1) grow0 = kMQ - 1;
        if (grow1 > kMQ - 1) grow1 = kMQ - 1;
        const float* q0p = qkv + (size_t)grow0 * 768 + h * kDH;
        const float* q1p = qkv + (size_t)grow1 * 768 + h * kDH;
#pragma unroll
        for (int ks = 0; ks < 4; ++ks) {
            qf[ks][0] = __float_as_uint(q0p[ks * 8 + tg]);
            qf[ks][1] = __float_as_uint(q1p[ks * 8 + tg]);
            qf[ks][2] = __float_as_uint(q0p[ks * 8 + tg + 4]);
            qf[ks][3] = __float_as_uint(q1p[ks * 8 + tg + 4]);
        }
    }
#pragma unroll 2
    for (int i = 0; i < 10; ++i) {
        const int n0 = (kq * 10 + i) * 8;
        if (n0 < 304) {
            int kr = n0 + g;
            if (kr >= kNQ) kr = 0;
            float c[4] = {0.f, 0.f, 0.f, 0.f};
            uint32_t bf[4][2];
#pragma unroll
            for (int ks = 0; ks < 4; ++ks) {
                bf[ks][0] = __float_as_uint(KV[kr * kKLD2 + ks * 8 + tg]);
                bf[ks][1] = __float_as_uint(KV[kr * kKLD2 + ks * 8 + tg + 4]);
            }
#pragma unroll
            for (int ks = 0; ks < 4; ++ks)
                mma_tf32(c, qf[ks], bf[ks]);
            const int col = n0 + tg * 2;
            *(float2*)&S[lr_g * kSLD + col] =
                make_float2(c[0] * scale, c[1] * scale);
            *(float2*)&S[(lr_g + 8) * kSLD + col] =
                make_float2(c[2] * scale, c[3] * scale);
        }
    }
    __syncthreads();

    for (int idx = tid; idx < kNQ * 8; idx += 256) {
        const int r = idx >> 3, c4 = (idx & 7) * 4;
        float4 v = *(const float4*)(qkv + ((size_t)(b * kNQ + r)) * 768 + 512 +
                                    h * kDH + c4);
        KV[(c4 + 0) * kVLD2 + r] = v.x;
        KV[(c4 + 1) * kVLD2 + r] = v.y;
        KV[(c4 + 2) * kVLD2 + r] = v.z;
        KV[(c4 + 3) * kVLD2 + r] = v.w;
    }
    if (tid < kDH * 4) {
        const int ch = tid >> 2, k = kNQ + (tid & 3);
        KV[ch * kVLD2 + k] = 0.f;
    }

    {
        const int row  = tid >> 2;
        const int part = tid & 3;
        if (row < kQT) {
            float* srow = &S[row * kSLD + part * 76];
            const int base_col = part * 76;
            float mx = -INFINITY;
#pragma unroll
            for (int i = 0; i < 19; ++i) {
                float4 v = *(const float4*)&srow[i * 4];
                const int c = base_col + i * 4;
                if (c + 0 < kNQ) mx = fmaxf(mx, v.x);
                if (c + 1 < kNQ) mx = fmaxf(mx, v.y);
                if (c + 2 < kNQ) mx = fmaxf(mx, v.z);
                if (c + 3 < kNQ) mx = fmaxf(mx, v.w);
            }
            mx = fmaxf(mx, __shfl_xor_sync(~0u, mx, 1));
            mx = fmaxf(mx, __shfl_xor_sync(~0u, mx, 2));
            float sum = 0.f;
#pragma unroll
            for (int i = 0; i < 19; ++i) {
                float4 v = *(const float4*)&srow[i * 4];
                const int c = base_col + i * 4;
                v.x = (c + 0 < kNQ) ? __expf(v.x - mx) : 0.f;
                v.y = (c + 1 < kNQ) ? __expf(v.y - mx) : 0.f;
                v.z = (c + 2 < kNQ) ? __expf(v.z - mx) : 0.f;
                v.w = (c + 3 < kNQ) ? __expf(v.w - mx) : 0.f;
                sum += (v.x + v.y) + (v.z + v.w);
                *(float4*)&srow[i * 4] = v;
            }
            sum += __shfl_xor_sync(~0u, sum, 1);
            sum += __shfl_xor_sync(~0u, sum, 2);
            if (part == 0) lrow[row] = 1.f / sum;
        }
    }
    __syncthreads();

    const int cgrp = w >> 1;
    const int n0 = cgrp * 8;
    float c[4] = {0.f, 0.f, 0.f, 0.f};
    {
        const float* Srow0 = &S[lr_g * kSLD];
        const float* Srow1 = &S[(lr_g + 8) * kSLD];
        const float* Vrow  = &KV[(n0 + g) * kVLD2];
        uint32_t afb[2][4], bfb[2][2];
        afb[0][0] = __float_as_uint(Srow0[tg]);
        afb[0][1] = __float_as_uint(Srow1[tg]);
        afb[0][2] = __float_as_uint(Srow0[tg + 4]);
        afb[0][3] = __float_as_uint(Srow1[tg + 4]);
        bfb[0][0] = __float_as_uint(Vrow[tg]);
        bfb[0][1] = __float_as_uint(Vrow[tg + 4]);
#pragma unroll
        for (int kt = 0; kt < 38; ++kt) {
            const int cur = kt & 1, nxt = cur ^ 1;
            if (kt < 37) {
                const int k = (kt + 1) * 8;
                afb[nxt][0] = __float_as_uint(Srow0[k + tg]);
                afb[nxt][1] = __float_as_uint(Srow1[k + tg]);
                afb[nxt][2] = __float_as_uint(Srow0[k + tg + 4]);
                afb[nxt][3] = __float_as_uint(Srow1[k + tg + 4]);
                bfb[nxt][0] = __float_as_uint(Vrow[k + tg]);
                bfb[nxt][1] = __float_as_uint(Vrow[k + tg + 4]);
            }
            mma_tf32(c, afb[cur], bfb[cur]);
        }
    }
    {
        const int qrow0 = q0 + lr_g, qrow1 = qrow0 + 8;
        const int col = n0 + tg * 2;
        if (qrow0 < kNQ) {
            const float inv = lrow[lr_g];
            *(float2*)(o + ((size_t)(b * kNQ + qrow0)) * kD + h * kDH + col) =
                make_float2(c[0] * inv, c[1] * inv);
        }
        if (qrow1 < kNQ) {
            const float inv = lrow[lr_g + 8];
            *(float2*)(o + ((size_t)(b * kNQ + qrow1)) * kD + h * kDH + col) =
                make_float2(c[2] * inv, c[3] * inv);
        }
    }
}

// ---------------------------------------------------------------------------
// MS deformable aggregation. Corner loads batched ahead of FMAs (MLP=8).
// ---------------------------------------------------------------------------
__global__ void msdeform_agg_kernel(const float* __restrict__ ref,
                                    const float* __restrict__ oa,
                                    const float* __restrict__ memory,
                                    float* __restrict__ agg) {
    const int bq = blockIdx.x;
    const int b = bq / kNQ;
    const int t = threadIdx.x;
    const int h = t >> 5;
    const int lane = t & 31;

    __shared__ float s_p[kNH][16];

    float lw = (lane < 16) ? oa[(size_t)bq * kOW + 256 + h * 16 + lane] : -INFINITY;
    float m = lw;
#pragma unroll
    for (int o = 8; o > 0; o >>= 1) m = fmaxf(m, __shfl_xor_sync(~0u, m, o, 16));
    float e = (lane < 16) ? expf(lw - m) : 0.f;
    float sum = e;
#pragma unroll
    for (int o = 8; o > 0; o >>= 1) sum += __shfl_xor_sync(~0u, sum, o, 16);
    if (lane < 16) s_p[h][lane] = e / sum;
    __syncwarp();

    const int cH[kNL]  = {100, 50, 25, 13};
    const int cW[kNL]  = {150, 75, 38, 19};
    const int cS0[kNL] = {0, 15000, 18750, 19700};

    float a0 = 0.f, a1 = 0.f, a2 = 0.f, a3 = 0.f;
    float a4 = 0.f, a5 = 0.f, a6 = 0.f, a7 = 0.f;
    float bsum = 0.f;

    const float* mbase = memory + (size_t)b * kS * kD + lane * 8;

#pragma unroll
    for (int l = 0; l < kNL; ++l) {
        const float rx = ref[((size_t)bq * kNL + l) * 2 + 0];
        const float ry = ref[((size_t)bq * kNL + l) * 2 + 1];
        const int Hl = cH[l], Wl = cW[l], s0 = cS0[l];
        const float fW = (float)Wl, fH = (float)Hl;
#pragma unroll
        for (int p = 0; p < kNP; ++p) {
            const float aw = s_p[h][l * kNP + p];
            const size_t ob = (size_t)bq * kOW + (((h * kNL + l) * kNP + p) * 2);
            const float ox = oa[ob + 0];
            const float oy = oa[ob + 1];
            const float x = (rx + ox / fW) * fW - 0.5f;
            const float y = (ry + oy / fH) * fH - 0.5f;
            const float x0f = floorf(x), y0f = floorf(y);
            const float tx = x - x0f, ty = y - y0f;
            const int x0 = (int)x0f, y0 = (int)y0f;

            float wgt[4];
            const float4* rp[4];
#pragma unroll
            for (int cc = 0; cc < 4; ++cc) {
                const int dy = cc >> 1, dx = cc & 1;
                const int xi = x0 + dx, yi = y0 + dy;
                const bool valid =
                    (xi >= 0) & (xi < Wl) & (yi >= 0) & (yi < Hl);
                wgt[cc] = valid
                    ? aw * (dy ? ty : (1.f - ty)) * (dx ? tx : (1.f - tx))
                    : 0.f;
                const int row = valid ? (s0 + yi * Wl + xi) : s0;
                rp[cc] = (const float4*)(mbase + (size_t)row * kD);
            }
            float4 v0[4], v1[4];
#pragma unroll
            for (int cc = 0; cc < 4; ++cc) { v0[cc] = rp[cc][0]; v1[cc] = rp[cc][1]; }
#pragma unroll
            for (int cc = 0; cc < 4; ++cc) {
                const float wv = wgt[cc];
                a0 = fmaf(wv, v0[cc].x, a0); a1 = fmaf(wv, v0[cc].y, a1);
                a2 = fmaf(wv, v0[cc].z, a2); a3 = fmaf(wv, v0[cc].w, a3);
                a4 = fmaf(wv, v1[cc].x, a4); a5 = fmaf(wv, v1[cc].y, a5);
                a6 = fmaf(wv, v1[cc].z, a6); a7 = fmaf(wv, v1[cc].w, a7);
                bsum += wv;
            }
        }
    }

    float* hb = agg + (size_t)bq * kAK2 + h * kHK;
    float4* dst = (float4*)(hb + lane * 8);
    dst[0] = make_float4(a0, a1, a2, a3);
    dst[1] = make_float4(a4, a5, a6, a7);
    if (lane == 0) hb[256] = bsum;
    else hb[256 + lane] = 0.f;
}

// ---------------------------------------------------------------------------
// Launch helpers
// ---------------------------------------------------------------------------
static void ensure_attrs() {
    static bool done = false;
    if (done) return;
    cudaFuncSetAttribute((const void*)gemm_tf32_kernel<3, false, 1>,
                         cudaFuncAttributeMaxDynamicSharedMemorySize,
                         gemm_smem_bytes<3>());
    cudaFuncSetAttribute((const void*)gemm_tf32_kernel<3, true, 1>,
                         cudaFuncAttributeMaxDynamicSharedMemorySize,
                         gemm_smem_bytes<3>());
    cudaFuncSetAttribute((const void*)gemm_tf32_kernel<3, false, 2>,
                         cudaFuncAttributeMaxDynamicSharedMemorySize,
                         gemm_smem_bytes<3>());
    cudaFuncSetAttribute((const void*)gemm_ln_kernel<true>,
                         cudaFuncAttributeMaxDynamicSharedMemorySize,
                         gemm_ln_smem_bytes());
    cudaFuncSetAttribute((const void*)gemm_ln_kernel<false>,
                         cudaFuncAttributeMaxDynamicSharedMemorySize,
                         gemm_ln_smem_bytes());
    cudaFuncSetAttribute((const void*)attn_tc_kernel,
                         cudaFuncAttributeMaxDynamicSharedMemorySize,
                         ATTN_SMEM);
    done = true;
}

static inline void launch_gemm(const float* A, const float* W, const float* b,
                               float* C, int M, int N, int K, bool relu) {
    dim3 grid(N / 64, (M + 63) / 64);
    if (relu)
        gemm_tf32_kernel<3, true, 1><<<grid, 256, gemm_smem_bytes<3>()>>>(
            A, A, N, W, b, C, M, N, K);
    else
        gemm_tf32_kernel<3, false, 1><<<grid, 256, gemm_smem_bytes<3>()>>>(
            A, A, N, W, b, C, M, N, K);
}

extern "C" void kernel_launch(void* const* d_in, const int* in_sizes, int n_in,
                              void* d_out, int out_size) {
    const float* tgt    = (const float*)d_in[0];
    const float* pos    = (const float*)d_in[1];
    const float* ref    = (const float*)d_in[2];
    const float* memory = (const float*)d_in[3];
    const float* in_w  = (const float*)d_in[7];
    const float* in_b  = (const float*)d_in[8];
    const float* out_w = (const float*)d_in[9];
    const float* out_b = (const float*)d_in[10];
    const float* n1g = (const float*)d_in[11];
    const float* n1b = (const float*)d_in[12];
    const float* n2g = (const float*)d_in[13];
    const float* n2b = (const float*)d_in[14];
    const float* n3g = (const float*)d_in[15];
    const float* n3b = (const float*)d_in[16];
    const float* so_w = (const float*)d_in[17];
    const float* so_b = (const float*)d_in[18];
    const float* aw_w = (const float*)d_in[19];
    const float* aw_b = (const float*)d_in[20];
    const float* v_w  = (const float*)d_in[21];
    const float* v_b  = (const float*)d_in[22];
    const float* op_w = (const float*)d_in[23];
    const float* op_b = (const float*)d_in[24];
    const float* l1w  = (const float*)d_in[25];
    const float* l1b  = (const float*)d_in[26];
    const float* l2w  = (const float*)d_in[27];
    const float* l2b  = (const float*)d_in[28];

    float* scratch = nullptr;
    cudaGetSymbolAddress((void**)&scratch, g_scratch);
    ensure_attrs();

    float* s_qkadd = scratch + OFF_QKADD;
    float* s_qkv   = scratch + OFF_QKV;
    float* s_attn  = scratch + OFF_ATTN;
    float* s_tgt1  = scratch + OFF_TGT1;
    float* s_query = scratch + OFF_QUERY;
    float* s_oa    = scratch + OFF_OA;
    float* s_tgt2  = scratch + OFF_TGT2;
    float* s_hid   = scratch + OFF_HID;
    float* s_ffo   = scratch + OFF_FFO;
    float* s_y     = scratch + OFF_Y;
    float* s_agg   = scratch + OFF_AGG;
    float* s_wv2   = scratch + OFF_WV2;
    float* s_wcat  = scratch + OFF_WCAT;
    float* s_bcat  = scratch + OFF_BCAT;

    const int nQD = kMQ * kD;

    // ---- zero split-K accumulation target (FFN2) ----
    cudaMemsetAsync(s_ffo, 0, (size_t)kMQ * kD * sizeof(float));

    // ---- precompute (Wv2, weight concat) + qkadd ----
    {
        dim3 grid(kNH, 9);
        precompute_kernel<<<grid, 256>>>(v_w, v_b, so_w, so_b, aw_w, aw_b,
                                         s_wv2, s_wcat, s_bcat);
    }
    add_kernel<<<(nQD + 255) / 256, 256>>>(tgt, pos, s_qkadd, nQD);

    // ---- self attention: merged QKV GEMM + tensor-core attention ----
    {
        dim3 grid(768 / 64, (kMQ + 63) / 64);
        gemm_tf32_kernel<3, false, 1><<<grid, 256, gemm_smem_bytes<3>()>>>(
            s_qkadd, tgt, 512, in_w, in_b, s_qkv, kMQ, 768, kD);
    }
    {
        dim3 grid((kNQ + kQT - 1) / kQT, kNH, kBS);
        attn_tc_kernel<<<grid, 256, ATTN_SMEM>>>(s_qkv, s_attn);
    }
    // fused out-proj + residual + LN + (+pos second output)
    gemm_ln_kernel<true><<<kMQ / 16, 256, gemm_ln_smem_bytes()>>>(
        s_attn, out_w, out_b, tgt, n2g, n2b, pos, s_tgt1, s_query, kD);

    // ---- MS deformable attention (factored rank-32 projection) ----
    launch_gemm(s_query, s_wcat, s_bcat, s_oa, kMQ, kOW, kD, false);
    msdeform_agg_kernel<<<kMQ, 256>>>(ref, s_oa, memory, s_agg);
    {
        dim3 grid((kMQ + 63) / 64, kNH);
        gemm_stage1_kernel<<<grid, 256, stage1_smem_bytes()>>>(s_agg, s_wv2, s_y);
    }
    // fused op-proj + residual + LN
    gemm_ln_kernel<false><<<kMQ / 16, 256, gemm_ln_smem_bytes()>>>(
        s_y, op_w, op_b, s_tgt1, n1g, n1b, nullptr, s_tgt2, nullptr, kD);

    // ---- FFN ----
    launch_gemm(s_tgt2, l1w, l1b, s_hid, kMQ, kDFF, kD, true);
    {
        dim3 grid(kD / 64, (kMQ + 63) / 64, 2);
        gemm_tf32_kernel<3, false, 2><<<grid, 256, gemm_smem_bytes<3>()>>>(
            s_hid, s_hid, kD, l2w, l2b, s_ffo, kMQ, kD, kDFF);
    }
    add_ln_kernel<<<kMQ, 256>>>(s_tgt2, s_ffo, n3g, n3b, (float*)d_out);
}

// round 17
// speedup vs baseline: 1.0187x; 1.0187x over previous
#include <cuda_runtime.h>
#include <math.h>
#include <stdint.h>

// ---------------------------------------------------------------------------
// Problem constants
// ---------------------------------------------------------------------------
namespace {
constexpr int kD   = 256;
constexpr int kNH  = 8;
constexpr int kDH  = 32;
constexpr int kNL  = 4;
constexpr int kNP  = 4;
constexpr int kDFF = 1024;
constexpr int kBS  = 8;
constexpr int kNQ  = 300;
constexpr int kS   = 19947;
constexpr int kMQ  = kBS * kNQ;      // 2400
constexpr int kHK  = 288;            // per-head agg K: 256 + bsum + 31 pad
constexpr int kAK2 = kNH * kHK;      // 2304 agg row width
constexpr int kOW  = 384;            // merged offs(256) + awl(128) width

constexpr size_t OFF_QKADD = 0;
constexpr size_t OFF_QKV   = OFF_QKADD + (size_t)kMQ * kD;   // [2400][768]
constexpr size_t OFF_ATTN  = OFF_QKV   + (size_t)kMQ * 768;
constexpr size_t OFF_SA    = OFF_ATTN  + (size_t)kMQ * kD;
constexpr size_t OFF_TGT1  = OFF_SA    + (size_t)kMQ * kD;
constexpr size_t OFF_QUERY = OFF_TGT1  + (size_t)kMQ * kD;
constexpr size_t OFF_OA    = OFF_QUERY + (size_t)kMQ * kD;   // [2400][384]
constexpr size_t OFF_T2    = OFF_OA    + (size_t)kMQ * kOW;
constexpr size_t OFF_TGT2  = OFF_T2    + (size_t)kMQ * kD;
constexpr size_t OFF_HID   = OFF_TGT2  + (size_t)kMQ * kD;
constexpr size_t OFF_FFO   = OFF_HID   + (size_t)kMQ * kDFF;
constexpr size_t OFF_Y     = OFF_FFO   + (size_t)kMQ * kD;   // [2400][256]
constexpr size_t OFF_AGG   = OFF_Y     + (size_t)kMQ * kD;   // [2400][2304]
constexpr size_t OFF_WV2   = OFF_AGG   + (size_t)kMQ * kAK2; // [8][32][288]
constexpr size_t OFF_WCAT  = OFF_WV2   + (size_t)kNH * 32 * kHK;
constexpr size_t OFF_BCAT  = OFF_WCAT  + (size_t)kOW * kD;   // [384]
constexpr size_t SCRATCH_TOTAL = OFF_BCAT + kOW;
} // namespace

__device__ float g_scratch[SCRATCH_TOTAL];

// ---------------------------------------------------------------------------
// helpers
// ---------------------------------------------------------------------------
__device__ __forceinline__ uint32_t smem_u32(const void* p) {
    uint32_t a;
    asm("{ .reg .u64 t; cvta.to.shared.u64 t, %1; cvt.u32.u64 %0, t; }"
        : "=r"(a) : "l"(p));
    return a;
}

__device__ __forceinline__ void cp_async16(uint32_t dst, const void* src, bool pred) {
    int sz = pred ? 16 : 0;
    asm volatile("cp.async.cg.shared.global [%0], [%1], 16, %2;"
                 :: "r"(dst), "l"(src), "r"(sz));
}
__device__ __forceinline__ void cp_commit() {
    asm volatile("cp.async.commit_group;");
}
template <int N>
__device__ __forceinline__ void cp_wait() {
    asm volatile("cp.async.wait_group %0;" :: "n"(N));
}

__device__ __forceinline__ void mma_tf32(float (&d)[4],
                                         const uint32_t (&a)[4],
                                         const uint32_t (&b)[2]) {
    asm volatile(
        "mma.sync.aligned.m16n8k8.row.col.f32.tf32.tf32.f32 "
        "{%0,%1,%2,%3}, {%4,%5,%6,%7}, {%8,%9}, {%0,%1,%2,%3};"
        : "+f"(d[0]), "+f"(d[1]), "+f"(d[2]), "+f"(d[3])
        : "r"(a[0]), "r"(a[1]), "r"(a[2]), "r"(a[3]),
          "r"(b[0]), "r"(b[1]));
}

// ---------------------------------------------------------------------------
// TF32 tensor-core GEMM with per-n-region A select and optional split-K.
// ---------------------------------------------------------------------------
template <int STAGES, bool RELU, int SPLITK>
__global__ __launch_bounds__(256, 2)
void gemm_tf32_kernel(const float* __restrict__ A1,
                      const float* __restrict__ A2,
                      int n_split,
                      const float* __restrict__ W,
                      const float* __restrict__ bias,
                      float* __restrict__ C,
                      int M, int N, int K) {
    constexpr int BM = 64, BN = 64, BK = 32;
    constexpr int LD = BK + 4;                 // 36 words/row
    constexpr int THREADS = 256;
    constexpr int WM = 2;
    constexpr int MT = 2, NT = 2;
    constexpr int A_IT = (BM * BK / 4) / THREADS;   // 2
    constexpr int B_IT = (BN * BK / 4) / THREADS;   // 2

    extern __shared__ float smem[];
    float* As = smem;
    float* Ws = smem + (size_t)STAGES * BM * LD;

    const int tid  = threadIdx.x;
    const int warp = tid >> 5;
    const int lane = tid & 31;
    const int g    = lane >> 2;
    const int tg   = lane & 3;
    const int tm   = blockIdx.y * BM;
    const int tn   = blockIdx.x * BN;
    const int wm   = (warp % WM) * 32;
    const int wn   = (warp / WM) * 16;

    const float* A = (tn < n_split) ? A1 : A2;

    const int nk_all = K / BK;
    const int nk_per = (nk_all + SPLITK - 1) / SPLITK;
    const int k_lo   = (SPLITK > 1) ? blockIdx.z * nk_per : 0;
    const int k_hi   = (SPLITK > 1) ? ((k_lo + nk_per < nk_all) ? k_lo + nk_per
                                                                : nk_all)
                                    : nk_all;
    const int nk_this = k_hi - k_lo;

    float acc[MT][NT][4] = {};

    auto issue = [&](int s, int kt) {
        if (kt < nk_this) {
            const int k0 = (k_lo + kt) * BK;
#pragma unroll
            for (int i = 0; i < A_IT; ++i) {
                int idx = tid + i * THREADS;
                int r = idx >> 3, c4 = (idx & 7) * 4;
                int gr = tm + r;
                cp_async16(smem_u32(&As[(size_t)s * BM * LD + r * LD + c4]),
                           A + (size_t)gr * K + k0 + c4, gr < M);
            }
#pragma unroll
            for (int i = 0; i < B_IT; ++i) {
                int idx = tid + i * THREADS;
                int r = idx >> 3, c4 = (idx & 7) * 4;
                cp_async16(smem_u32(&Ws[(size_t)s * BN * LD + r * LD + c4]),
                           W + (size_t)(tn + r) * K + k0 + c4, true);
            }
        }
        cp_commit();
    };

    issue(0, 0);
#pragma unroll
    for (int p = 1; p < STAGES - 1; ++p) issue(p, p);

    for (int kt = 0; kt < nk_this; ++kt) {
        const int s = kt % STAGES;
        cp_wait<STAGES - 2>();
        __syncthreads();
        issue((kt + STAGES - 1) % STAGES, kt + STAGES - 1);

        const float* as = &As[(size_t)s * BM * LD];
        const float* ws = &Ws[(size_t)s * BN * LD];
#pragma unroll
        for (int ks = 0; ks < 4; ++ks) {
            const int kc = ks * 8 + tg;
            uint32_t af[MT][4], bf[NT][2];
#pragma unroll
            for (int mt = 0; mt < MT; ++mt) {
                const int r = wm + mt * 16 + g;
                af[mt][0] = __float_as_uint(as[r * LD + kc]);
                af[mt][1] = __float_as_uint(as[(r + 8) * LD + kc]);
                af[mt][2] = __float_as_uint(as[r * LD + kc + 4]);
                af[mt][3] = __float_as_uint(as[(r + 8) * LD + kc + 4]);
            }
#pragma unroll
            for (int nt = 0; nt < NT; ++nt) {
                const int n = wn + nt * 8 + g;
                bf[nt][0] = __float_as_uint(ws[n * LD + kc]);
                bf[nt][1] = __float_as_uint(ws[n * LD + kc + 4]);
            }
#pragma unroll
            for (int mt = 0; mt < MT; ++mt)
#pragma unroll
                for (int nt = 0; nt < NT; ++nt)
                    mma_tf32(acc[mt][nt], af[mt], bf[nt]);
        }
        __syncthreads();
    }

    const bool add_bias = (SPLITK == 1) || (blockIdx.z == 0);
#pragma unroll
    for (int mt = 0; mt < MT; ++mt) {
        const int gr0 = tm + wm + mt * 16 + g;
        const int gr1 = gr0 + 8;
#pragma unroll
        for (int nt = 0; nt < NT; ++nt) {
            const int gc = tn + wn + nt * 8 + tg * 2;
            const float b0 = add_bias ? bias[gc] : 0.f;
            const float b1 = add_bias ? bias[gc + 1] : 0.f;
            if (gr0 < M) {
                float v0 = acc[mt][nt][0] + b0;
                float v1 = acc[mt][nt][1] + b1;
                if (RELU) { v0 = fmaxf(v0, 0.f); v1 = fmaxf(v1, 0.f); }
                if (SPLITK == 1) {
                    *(float2*)(C + (size_t)gr0 * N + gc) = make_float2(v0, v1);
                } else {
                    atomicAdd(C + (size_t)gr0 * N + gc, v0);
                    atomicAdd(C + (size_t)gr0 * N + gc + 1, v1);
                }
            }
            if (gr1 < M) {
                float v2 = acc[mt][nt][2] + b0;
                float v3 = acc[mt][nt][3] + b1;
                if (RELU) { v2 = fmaxf(v2, 0.f); v3 = fmaxf(v3, 0.f); }
                if (SPLITK == 1) {
                    *(float2*)(C + (size_t)gr1 * N + gc) = make_float2(v2, v3);
                } else {
                    atomicAdd(C + (size_t)gr1 * N + gc, v2);
                    atomicAdd(C + (size_t)gr1 * N + gc + 1, v3);
                }
            }
        }
    }
}

template <int STAGES>
constexpr int gemm_smem_bytes() { return STAGES * 128 * 36 * 4; }

// ---------------------------------------------------------------------------
// Stage-1 batched head GEMM: y[m][h*32+j] = agg[m][h*288..] @ Wv2[h][j][.]^T
// ---------------------------------------------------------------------------
__global__ __launch_bounds__(256, 2)
void gemm_stage1_kernel(const float* __restrict__ agg,
                        const float* __restrict__ wv2,
                        float* __restrict__ y) {
    constexpr int BM = 64, BN = 32, BK = 32, STAGES = 3;
    constexpr int LD = BK + 4;
    constexpr int THREADS = 256;
    constexpr int NK = kHK / BK;                 // 9

    extern __shared__ float smem[];
    float* As = smem;
    float* Ws = smem + (size_t)STAGES * BM * LD;

    const int tid  = threadIdx.x;
    const int warp = tid >> 5;
    const int lane = tid & 31;
    const int g    = lane >> 2;
    const int tg   = lane & 3;
    const int tm   = blockIdx.x * BM;
    const int h    = blockIdx.y;
    const int wm   = (warp & 1) * 32;
    const int wn   = (warp >> 1) * 8;

    const float* A = agg + (size_t)h * kHK;
    const float* W = wv2 + (size_t)h * 32 * kHK;

    float acc[2][4] = {};

    auto issue = [&](int s, int kt) {
        if (kt < NK) {
            const int k0 = kt * BK;
#pragma unroll
            for (int i = 0; i < 2; ++i) {
                int idx = tid + i * THREADS;
                int r = idx >> 3, c4 = (idx & 7) * 4;
                int gr = tm + r;
                cp_async16(smem_u32(&As[(size_t)s * BM * LD + r * LD + c4]),
                           A + (size_t)gr * kAK2 + k0 + c4, gr < kMQ);
            }
            {
                int r = tid >> 3, c4 = (tid & 7) * 4;
                cp_async16(smem_u32(&Ws[(size_t)s * BN * LD + r * LD + c4]),
                           W + (size_t)r * kHK + k0 + c4, true);
            }
        }
        cp_commit();
    };

    issue(0, 0);
    issue(1, 1);

    for (int kt = 0; kt < NK; ++kt) {
        const int s = kt % STAGES;
        cp_wait<1>();
        __syncthreads();
        issue((kt + 2) % STAGES, kt + 2);

        const float* as = &As[(size_t)s * BM * LD];
        const float* ws = &Ws[(size_t)s * BN * LD];
#pragma unroll
        for (int ks = 0; ks < 4; ++ks) {
            const int kc = ks * 8 + tg;
            uint32_t af[4], bf[2];
            const int r = wm + g;
            af[0] = __float_as_uint(as[r * LD + kc]);
            af[1] = __float_as_uint(as[(r + 8) * LD + kc]);
            af[2] = __float_as_uint(as[r * LD + kc + 4]);
            af[3] = __float_as_uint(as[(r + 8) * LD + kc + 4]);
            const int n = wn + g;
            bf[0] = __float_as_uint(ws[n * LD + kc]);
            bf[1] = __float_as_uint(ws[n * LD + kc + 4]);
            mma_tf32(acc[0], af, bf);
            const int r2 = r + 16;
            af[0] = __float_as_uint(as[r2 * LD + kc]);
            af[1] = __float_as_uint(as[(r2 + 8) * LD + kc]);
            af[2] = __float_as_uint(as[r2 * LD + kc + 4]);
            af[3] = __float_as_uint(as[(r2 + 8) * LD + kc + 4]);
            mma_tf32(acc[1], af, bf);
        }
        __syncthreads();
    }

#pragma unroll
    for (int mt = 0; mt < 2; ++mt) {
        const int gr0 = tm + wm + mt * 16 + g;
        const int gr1 = gr0 + 8;
        const int gc = h * 32 + wn + tg * 2;
        if (gr0 < kMQ)
            *(float2*)(y + (size_t)gr0 * kD + gc) =
                make_float2(acc[mt][0], acc[mt][1]);
        if (gr1 < kMQ)
            *(float2*)(y + (size_t)gr1 * kD + gc) =
                make_float2(acc[mt][2], acc[mt][3]);
    }
}

constexpr int stage1_smem_bytes() { return 3 * (64 + 32) * 36 * 4; }

// ---------------------------------------------------------------------------
// Precompute kernel. grid = (8, 9), block = 256.
// ---------------------------------------------------------------------------
__global__ void precompute_kernel(const float* __restrict__ v_w,
                                  const float* __restrict__ v_b,
                                  const float* __restrict__ so_w,
                                  const float* __restrict__ so_b,
                                  const float* __restrict__ aw_w,
                                  const float* __restrict__ aw_b,
                                  float* __restrict__ wv2,
                                  float* __restrict__ wcat,
                                  float* __restrict__ bcat) {
    const int tid = threadIdx.x;
    if (blockIdx.y == 8) {
        const int r0 = blockIdx.x * 48;
        for (int r = r0; r < r0 + 48; ++r) {
            const float* src = (r < 256) ? (so_w + (size_t)r * 256)
                                         : (aw_w + (size_t)(r - 256) * 256);
            wcat[(size_t)r * 256 + tid] = src[tid];
        }
        if (tid < 48) {
            int r = r0 + tid;
            bcat[r] = (r < 256) ? so_b[r] : aw_b[r - 256];
        }
        return;
    }
    if (blockIdx.x > 0) return;
    const int h = blockIdx.y;
    float* dst = wv2 + (size_t)h * 32 * kHK;
    for (int idx = tid; idx < 32 * kHK; idx += 256) {
        const int j = idx / kHK, c = idx % kHK;
        float v = 0.f;
        if (c < 256)      v = v_w[(size_t)(32 * h + j) * 256 + c];
        else if (c == 256) v = v_b[32 * h + j];
        dst[idx] = v;
    }
}

// ---------------------------------------------------------------------------
// Elementwise add
// ---------------------------------------------------------------------------
__global__ void add_kernel(const float* __restrict__ a,
                           const float* __restrict__ b,
                           float* __restrict__ out, int n) {
    int i = blockIdx.x * blockDim.x + threadIdx.x;
    if (i < n) out[i] = a[i] + b[i];
}

// ---------------------------------------------------------------------------
// Residual + LayerNorm (256 features, one block per row).
// ---------------------------------------------------------------------------
template <bool WITH_POS>
__global__ void add_ln_kernel(const float* __restrict__ x,
                              const float* __restrict__ r,
                              const float* __restrict__ g,
                              const float* __restrict__ bta,
                              float* __restrict__ out,
                              const float* __restrict__ pos,
                              float* __restrict__ out2) {
    const int row = blockIdx.x;
    const int t = threadIdx.x;
    const size_t base = (size_t)row * kD;
    float v = x[base + t] + r[base + t];

    __shared__ float sm[8];
    float s = v;
#pragma unroll
    for (int o = 16; o > 0; o >>= 1) s += __shfl_xor_sync(~0u, s, o);
    if ((t & 31) == 0) sm[t >> 5] = s;
    __syncthreads();
    float tot = 0.f;
#pragma unroll
    for (int i = 0; i < 8; ++i) tot += sm[i];
    const float mean = tot * (1.f / kD);
    const float d = v - mean;
    float s2 = d * d;
#pragma unroll
    for (int o = 16; o > 0; o >>= 1) s2 += __shfl_xor_sync(~0u, s2, o);
    __syncthreads();
    if ((t & 31) == 0) sm[t >> 5] = s2;
    __syncthreads();
    float tot2 = 0.f;
#pragma unroll
    for (int i = 0; i < 8; ++i) tot2 += sm[i];
    const float var = tot2 * (1.f / kD);
    const float o1 = d * rsqrtf(var + 1e-5f) * g[t] + bta[t];
    out[base + t] = o1;
    if (WITH_POS) out2[base + t] = o1 + pos[base + t];
}

// ---------------------------------------------------------------------------
// Tensor-core self attention, 32-query tile, software-pipelined fragments.
// ---------------------------------------------------------------------------
namespace {
constexpr int kQT   = 32;
constexpr int kSLD  = 316;
constexpr int kKLD2 = 36;
constexpr int kVLD2 = 308;
constexpr int S_FLOATS  = kQT * kSLD;
constexpr int KV_FLOATS = kNQ * kKLD2;
constexpr int ATTN_SMEM = (S_FLOATS + KV_FLOATS + kQT) * 4;  // 83776 B
}

__global__ __launch_bounds__(256, 2)
void attn_tc_kernel(const float* __restrict__ qkv, float* __restrict__ o) {
    extern __shared__ float sm[];
    float* S    = sm;
    float* KV   = sm + S_FLOATS;
    float* lrow = KV + KV_FLOATS;

    const int tid  = threadIdx.x;
    const int w    = tid >> 5;
    const int lane = tid & 31;
    const int g    = lane >> 2;
    const int tg   = lane & 3;
    const int h  = blockIdx.y;
    const int b  = blockIdx.z;
    const int q0 = blockIdx.x * kQT;
    const float scale = 0.1767766952966369f;

    for (int idx = tid; idx < kNQ * 8; idx += 256) {
        const int r = idx >> 3, c4 = (idx & 7) * 4;
        *(float4*)&KV[r * kKLD2 + c4] =
            *(const float4*)(qkv + ((size_t)(b * kNQ + r)) * 768 + 256 +
                             h * kDH + c4);
    }
    __syncthreads();

    const int mstrip = w & 1;
    const int lr_g   = mstrip * 16 + g;
    const int kq     = w >> 1;
    uint32_t qf[4][4];
    {
        int grow0 = b * kNQ + q0 + lr_g;
        int grow1 = grow0 + 8;
        if (grow0 > kMQ - 1) grow0 = kMQ - 1;
        if (grow1 > kMQ - 1) grow1 = kMQ - 1;
        const float* q0p = qkv + (size_t)grow0 * 768 + h * kDH;
        const float* q1p = qkv + (size_t)grow1 * 768 + h * kDH;
#pragma unroll
        for (int ks = 0; ks < 4; ++ks) {
            qf[ks][0] = __float_as_uint(q0p[ks * 8 + tg]);
            qf[ks][1] = __float_as_uint(q1p[ks * 8 + tg]);
            qf[ks][2] = __float_as_uint(q0p[ks * 8 + tg + 4]);
            qf[ks][3] = __float_as_uint(q1p[ks * 8 + tg + 4]);
        }
    }
#pragma unroll 2
    for (int i = 0; i < 10; ++i) {
        const int n0 = (kq * 10 + i) * 8;
        if (n0 < 304) {
            int kr = n0 + g;
            if (kr >= kNQ) kr = 0;
            float c[4] = {0.f, 0.f, 0.f, 0.f};
            uint32_t bf[4][2];
#pragma unroll
            for (int ks = 0; ks < 4; ++ks) {
                bf[ks][0] = __float_as_uint(KV[kr * kKLD2 + ks * 8 + tg]);
                bf[ks][1] = __float_as_uint(KV[kr * kKLD2 + ks * 8 + tg + 4]);
            }
#pragma unroll
            for (int ks = 0; ks < 4; ++ks)
                mma_tf32(c, qf[ks], bf[ks]);
            const int col = n0 + tg * 2;
            *(float2*)&S[lr_g * kSLD + col] =
                make_float2(c[0] * scale, c[1] * scale);
            *(float2*)&S[(lr_g + 8) * kSLD + col] =
                make_float2(c[2] * scale, c[3] * scale);
        }
    }
    __syncthreads();

    for (int idx = tid; idx < kNQ * 8; idx += 256) {
        const int r = idx >> 3, c4 = (idx & 7) * 4;
        float4 v = *(const float4*)(qkv + ((size_t)(b * kNQ + r)) * 768 + 512 +
                                    h * kDH + c4);
        KV[(c4 + 0) * kVLD2 + r] = v.x;
        KV[(c4 + 1) * kVLD2 + r] = v.y;
        KV[(c4 + 2) * kVLD2 + r] = v.z;
        KV[(c4 + 3) * kVLD2 + r] = v.w;
    }
    if (tid < kDH * 4) {
        const int ch = tid >> 2, k = kNQ + (tid & 3);
        KV[ch * kVLD2 + k] = 0.f;
    }

    {
        const int row  = tid >> 2;
        const int part = tid & 3;
        if (row < kQT) {
            float* srow = &S[row * kSLD + part * 76];
            const int base_col = part * 76;
            float mx = -INFINITY;
#pragma unroll
            for (int i = 0; i < 19; ++i) {
                float4 v = *(const float4*)&srow[i * 4];
                const int c = base_col + i * 4;
                if (c + 0 < kNQ) mx = fmaxf(mx, v.x);
                if (c + 1 < kNQ) mx = fmaxf(mx, v.y);
                if (c + 2 < kNQ) mx = fmaxf(mx, v.z);
                if (c + 3 < kNQ) mx = fmaxf(mx, v.w);
            }
            mx = fmaxf(mx, __shfl_xor_sync(~0u, mx, 1));
            mx = fmaxf(mx, __shfl_xor_sync(~0u, mx, 2));
            float sum = 0.f;
#pragma unroll
            for (int i = 0; i < 19; ++i) {
                float4 v = *(const float4*)&srow[i * 4];
                const int c = base_col + i * 4;
                v.x = (c + 0 < kNQ) ? __expf(v.x - mx) : 0.f;
                v.y = (c + 1 < kNQ) ? __expf(v.y - mx) : 0.f;
                v.z = (c + 2 < kNQ) ? __expf(v.z - mx) : 0.f;
                v.w = (c + 3 < kNQ) ? __expf(v.w - mx) : 0.f;
                sum += (v.x + v.y) + (v.z + v.w);
                *(float4*)&srow[i * 4] = v;
            }
            sum += __shfl_xor_sync(~0u, sum, 1);
            sum += __shfl_xor_sync(~0u, sum, 2);
            if (part == 0) lrow[row] = 1.f / sum;
        }
    }
    __syncthreads();

    const int cgrp = w >> 1;
    const int n0 = cgrp * 8;
    float c[4] = {0.f, 0.f, 0.f, 0.f};
    {
        const float* Srow0 = &S[lr_g * kSLD];
        const float* Srow1 = &S[(lr_g + 8) * kSLD];
        const float* Vrow  = &KV[(n0 + g) * kVLD2];
        uint32_t afb[2][4], bfb[2][2];
        afb[0][0] = __float_as_uint(Srow0[tg]);
        afb[0][1] = __float_as_uint(Srow1[tg]);
        afb[0][2] = __float_as_uint(Srow0[tg + 4]);
        afb[0][3] = __float_as_uint(Srow1[tg + 4]);
        bfb[0][0] = __float_as_uint(Vrow[tg]);
        bfb[0][1] = __float_as_uint(Vrow[tg + 4]);
#pragma unroll
        for (int kt = 0; kt < 38; ++kt) {
            const int cur = kt & 1, nxt = cur ^ 1;
            if (kt < 37) {
                const int k = (kt + 1) * 8;
                afb[nxt][0] = __float_as_uint(Srow0[k + tg]);
                afb[nxt][1] = __float_as_uint(Srow1[k + tg]);
                afb[nxt][2] = __float_as_uint(Srow0[k + tg + 4]);
                afb[nxt][3] = __float_as_uint(Srow1[k + tg + 4]);
                bfb[nxt][0] = __float_as_uint(Vrow[k + tg]);
                bfb[nxt][1] = __float_as_uint(Vrow[k + tg + 4]);
            }
            mma_tf32(c, afb[cur], bfb[cur]);
        }
    }
    {
        const int qrow0 = q0 + lr_g, qrow1 = qrow0 + 8;
        const int col = n0 + tg * 2;
        if (qrow0 < kNQ) {
            const float inv = lrow[lr_g];
            *(float2*)(o + ((size_t)(b * kNQ + qrow0)) * kD + h * kDH + col) =
                make_float2(c[0] * inv, c[1] * inv);
        }
        if (qrow1 < kNQ) {
            const float inv = lrow[lr_g + 8];
            *(float2*)(o + ((size_t)(b * kNQ + qrow1)) * kD + h * kDH + col) =
                make_float2(c[2] * inv, c[3] * inv);
        }
    }
}

// ---------------------------------------------------------------------------
// MS deformable aggregation. Corner loads batched ahead of FMAs (MLP=8).
// ---------------------------------------------------------------------------
__global__ void msdeform_agg_kernel(const float* __restrict__ ref,
                                    const float* __restrict__ oa,
                                    const float* __restrict__ memory,
                                    float* __restrict__ agg) {
    const int bq = blockIdx.x;
    const int b = bq / kNQ;
    const int t = threadIdx.x;
    const int h = t >> 5;
    const int lane = t & 31;

    __shared__ float s_p[kNH][16];

    float lw = (lane < 16) ? oa[(size_t)bq * kOW + 256 + h * 16 + lane] : -INFINITY;
    float m = lw;
#pragma unroll
    for (int o = 8; o > 0; o >>= 1) m = fmaxf(m, __shfl_xor_sync(~0u, m, o, 16));
    float e = (lane < 16) ? expf(lw - m) : 0.f;
    float sum = e;
#pragma unroll
    for (int o = 8; o > 0; o >>= 1) sum += __shfl_xor_sync(~0u, sum, o, 16);
    if (lane < 16) s_p[h][lane] = e / sum;
    __syncwarp();

    const int cH[kNL]  = {100, 50, 25, 13};
    const int cW[kNL]  = {150, 75, 38, 19};
    const int cS0[kNL] = {0, 15000, 18750, 19700};

    float a0 = 0.f, a1 = 0.f, a2 = 0.f, a3 = 0.f;
    float a4 = 0.f, a5 = 0.f, a6 = 0.f, a7 = 0.f;
    float bsum = 0.f;

    const float* mbase = memory + (size_t)b * kS * kD + lane * 8;

#pragma unroll
    for (int l = 0; l < kNL; ++l) {
        const float rx = ref[((size_t)bq * kNL + l) * 2 + 0];
        const float ry = ref[((size_t)bq * kNL + l) * 2 + 1];
        const int Hl = cH[l], Wl = cW[l], s0 = cS0[l];
        const float fW = (float)Wl, fH = (float)Hl;
#pragma unroll
        for (int p = 0; p < kNP; ++p) {
            const float aw = s_p[h][l * kNP + p];
            const size_t ob = (size_t)bq * kOW + (((h * kNL + l) * kNP + p) * 2);
            const float ox = oa[ob + 0];
            const float oy = oa[ob + 1];
            const float x = (rx + ox / fW) * fW - 0.5f;
            const float y = (ry + oy / fH) * fH - 0.5f;
            const float x0f = floorf(x), y0f = floorf(y);
            const float tx = x - x0f, ty = y - y0f;
            const int x0 = (int)x0f, y0 = (int)y0f;

            float wgt[4];
            const float4* rp[4];
#pragma unroll
            for (int cc = 0; cc < 4; ++cc) {
                const int dy = cc >> 1, dx = cc & 1;
                const int xi = x0 + dx, yi = y0 + dy;
                const bool valid =
                    (xi >= 0) & (xi < Wl) & (yi >= 0) & (yi < Hl);
                wgt[cc] = valid
                    ? aw * (dy ? ty : (1.f - ty)) * (dx ? tx : (1.f - tx))
                    : 0.f;
                const int row = valid ? (s0 + yi * Wl + xi) : s0;
                rp[cc] = (const float4*)(mbase + (size_t)row * kD);
            }
            float4 v0[4], v1[4];
#pragma unroll
            for (int cc = 0; cc < 4; ++cc) { v0[cc] = rp[cc][0]; v1[cc] = rp[cc][1]; }
#pragma unroll
            for (int cc = 0; cc < 4; ++cc) {
                const float wv = wgt[cc];
                a0 = fmaf(wv, v0[cc].x, a0); a1 = fmaf(wv, v0[cc].y, a1);
                a2 = fmaf(wv, v0[cc].z, a2); a3 = fmaf(wv, v0[cc].w, a3);
                a4 = fmaf(wv, v1[cc].x, a4); a5 = fmaf(wv, v1[cc].y, a5);
                a6 = fmaf(wv, v1[cc].z, a6); a7 = fmaf(wv, v1[cc].w, a7);
                bsum += wv;
            }
        }
    }

    float* hb = agg + (size_t)bq * kAK2 + h * kHK;
    float4* dst = (float4*)(hb + lane * 8);
    dst[0] = make_float4(a0, a1, a2, a3);
    dst[1] = make_float4(a4, a5, a6, a7);
    if (lane == 0) hb[256] = bsum;
    else hb[256 + lane] = 0.f;
}

// ---------------------------------------------------------------------------
// Launch helpers
// ---------------------------------------------------------------------------
static void ensure_attrs() {
    static bool done = false;
    if (done) return;
    cudaFuncSetAttribute((const void*)gemm_tf32_kernel<3, false, 1>,
                         cudaFuncAttributeMaxDynamicSharedMemorySize,
                         gemm_smem_bytes<3>());
    cudaFuncSetAttribute((const void*)gemm_tf32_kernel<3, true, 1>,
                         cudaFuncAttributeMaxDynamicSharedMemorySize,
                         gemm_smem_bytes<3>());
    cudaFuncSetAttribute((const void*)gemm_tf32_kernel<3, false, 2>,
                         cudaFuncAttributeMaxDynamicSharedMemorySize,
                         gemm_smem_bytes<3>());
    cudaFuncSetAttribute((const void*)attn_tc_kernel,
                         cudaFuncAttributeMaxDynamicSharedMemorySize,
                         ATTN_SMEM);
    done = true;
}

static inline void launch_gemm(const float* A, const float* W, const float* b,
                               float* C, int M, int N, int K, bool relu) {
    dim3 grid(N / 64, (M + 63) / 64);
    if (relu)
        gemm_tf32_kernel<3, true, 1><<<grid, 256, gemm_smem_bytes<3>()>>>(
            A, A, N, W, b, C, M, N, K);
    else
        gemm_tf32_kernel<3, false, 1><<<grid, 256, gemm_smem_bytes<3>()>>>(
            A, A, N, W, b, C, M, N, K);
}

static inline void launch_gemm_sk2(const float* A, const float* W, const float* b,
                                   float* C, int M, int N, int K) {
    dim3 grid(N / 64, (M + 63) / 64, 2);
    gemm_tf32_kernel<3, false, 2><<<grid, 256, gemm_smem_bytes<3>()>>>(
        A, A, N, W, b, C, M, N, K);
}

extern "C" void kernel_launch(void* const* d_in, const int* in_sizes, int n_in,
                              void* d_out, int out_size) {
    const float* tgt    = (const float*)d_in[0];
    const float* pos    = (const float*)d_in[1];
    const float* ref    = (const float*)d_in[2];
    const float* memory = (const float*)d_in[3];
    const float* in_w  = (const float*)d_in[7];
    const float* in_b  = (const float*)d_in[8];
    const float* out_w = (const float*)d_in[9];
    const float* out_b = (const float*)d_in[10];
    const float* n1g = (const float*)d_in[11];
    const float* n1b = (const float*)d_in[12];
    const float* n2g = (const float*)d_in[13];
    const float* n2b = (const float*)d_in[14];
    const float* n3g = (const float*)d_in[15];
    const float* n3b = (const float*)d_in[16];
    const float* so_w = (const float*)d_in[17];
    const float* so_b = (const float*)d_in[18];
    const float* aw_w = (const float*)d_in[19];
    const float* aw_b = (const float*)d_in[20];
    const float* v_w  = (const float*)d_in[21];
    const float* v_b  = (const float*)d_in[22];
    const float* op_w = (const float*)d_in[23];
    const float* op_b = (const float*)d_in[24];
    const float* l1w  = (const float*)d_in[25];
    const float* l1b  = (const float*)d_in[26];
    const float* l2w  = (const float*)d_in[27];
    const float* l2b  = (const float*)d_in[28];

    float* scratch = nullptr;
    cudaGetSymbolAddress((void**)&scratch, g_scratch);
    ensure_attrs();

    float* s_qkadd = scratch + OFF_QKADD;
    float* s_qkv   = scratch + OFF_QKV;
    float* s_attn  = scratch + OFF_ATTN;
    float* s_sa    = scratch + OFF_SA;
    float* s_tgt1  = scratch + OFF_TGT1;
    float* s_query = scratch + OFF_QUERY;
    float* s_oa    = scratch + OFF_OA;
    float* s_t2    = scratch + OFF_T2;
    float* s_tgt2  = scratch + OFF_TGT2;
    float* s_hid   = scratch + OFF_HID;
    float* s_ffo   = scratch + OFF_FFO;
    float* s_y     = scratch + OFF_Y;
    float* s_agg   = scratch + OFF_AGG;
    float* s_wv2   = scratch + OFF_WV2;
    float* s_wcat  = scratch + OFF_WCAT;
    float* s_bcat  = scratch + OFF_BCAT;

    const int nQD = kMQ * kD;

    // ---- zero split-K accumulation targets ----
    cudaMemsetAsync(s_sa, 0, (size_t)kMQ * kD * sizeof(float));
    cudaMemsetAsync(s_t2, 0, (size_t)kMQ * kD * sizeof(float));
    cudaMemsetAsync(s_ffo, 0, (size_t)kMQ * kD * sizeof(float));

    // ---- precompute (Wv2, weight concat) + qkadd ----
    {
        dim3 grid(kNH, 9);
        precompute_kernel<<<grid, 256>>>(v_w, v_b, so_w, so_b, aw_w, aw_b,
                                         s_wv2, s_wcat, s_bcat);
    }
    add_kernel<<<(nQD + 255) / 256, 256>>>(tgt, pos, s_qkadd, nQD);

    // ---- self attention: merged QKV GEMM + tensor-core attention ----
    {
        dim3 grid(768 / 64, (kMQ + 63) / 64);
        gemm_tf32_kernel<3, false, 1><<<grid, 256, gemm_smem_bytes<3>()>>>(
            s_qkadd, tgt, 512, in_w, in_b, s_qkv, kMQ, 768, kD);
    }
    {
        dim3 grid((kNQ + kQT - 1) / kQT, kNH, kBS);
        attn_tc_kernel<<<grid, 256, ATTN_SMEM>>>(s_qkv, s_attn);
    }
    launch_gemm_sk2(s_attn, out_w, out_b, s_sa, kMQ, kD, kD);
    add_ln_kernel<true><<<kMQ, 256>>>(tgt, s_sa, n2g, n2b, s_tgt1, pos, s_query);

    // ---- MS deformable attention (factored rank-32 projection) ----
    launch_gemm(s_query, s_wcat, s_bcat, s_oa, kMQ, kOW, kD, false);
    msdeform_agg_kernel<<<kMQ, 256>>>(ref, s_oa, memory, s_agg);
    {
        dim3 grid((kMQ + 63) / 64, kNH);
        gemm_stage1_kernel<<<grid, 256, stage1_smem_bytes()>>>(s_agg, s_wv2, s_y);
    }
    launch_gemm_sk2(s_y, op_w, op_b, s_t2, kMQ, kD, kD);
    add_ln_kernel<false><<<kMQ, 256>>>(s_tgt1, s_t2, n1g, n1b, s_tgt2,
                                       nullptr, nullptr);

    // ---- FFN ----
    launch_gemm(s_tgt2, l1w, l1b, s_hid, kMQ, kDFF, kD, true);
    launch_gemm_sk2(s_hid, l2w, l2b, s_ffo, kMQ, kD, kDFF);
    add_ln_kernel<false><<<kMQ, 256>>>(s_tgt2, s_ffo, n3g, n3b, (float*)d_out,
                                       nullptr, nullptr);
}